// round 9
// baseline (speedup 1.0000x reference)
#include <cuda_runtime.h>
#include <stdint.h>

#define AN 196416
#define NC 80
#define KK 1000
#define CAP 2048
#define MPARTS 6
#define TOT4 (AN * NC / 4)          // 3,928,320 float4s
#define COLGRID 1184
#define T0 (254.0f / 256.0f)

// ---------------- global scratch ----------------
__device__ int                g_cnt[NC];
__device__ unsigned long long g_cand[NC * CAP];
__device__ float4             g_box  [NC * 1024];
__device__ float              g_score[NC * 1024];
__device__ unsigned           g_vb   [NC * 32];
__device__ unsigned           g_maskT[NC * 32 * 1024];   // [class][wordcol][row]
__device__ unsigned           g_diag [NC * 1024];

__device__ __forceinline__ unsigned order_key(float x) {
    unsigned u = __float_as_uint(x);
    return (u & 0x80000000u) ? ~u : (u | 0x80000000u);
}

// ---------------------------------------------------------------------------
// K0: zero per-class counters (graph replays need re-init)
// ---------------------------------------------------------------------------
__global__ void init_kernel() {
    if (threadIdx.x < NC) g_cnt[threadIdx.x] = 0;
}

// ---------------------------------------------------------------------------
// K1: chip-wide candidate collect from ORIGINAL [AN, NC] layout.
// ---------------------------------------------------------------------------
__global__ __launch_bounds__(256) void collect_kernel(const float* __restrict__ cls) {
    const float4* __restrict__ p4 = reinterpret_cast<const float4*>(cls);
    for (int i = blockIdx.x * 256 + threadIdx.x; i < TOT4; i += COLGRID * 256) {
        float4 v = p4[i];
        if (v.x >= T0 || v.y >= T0 || v.z >= T0 || v.w >= T0) {
            int f = i * 4;
            int a = f / NC;
            int c0 = f - a * NC;
#define PUSH(x, k)                                                            \
            if ((x) >= T0) {                                                  \
                int cc = c0 + (k);                                            \
                int pos = atomicAdd(&g_cnt[cc], 1);                           \
                if (pos < CAP)                                                \
                    g_cand[cc * CAP + pos] =                                  \
                        ((unsigned long long)(~order_key(x)) << 32)           \
                        | (unsigned)a;                                        \
            }
            PUSH(v.x, 0) PUSH(v.y, 1) PUSH(v.z, 2) PUSH(v.w, 3)
#undef PUSH
        }
    }
}

// ---------------------------------------------------------------------------
// K2: per-class sort + decode (fast path from g_cand; exact slow path rescue)
// ---------------------------------------------------------------------------
__device__ __forceinline__ unsigned long long bx_exch(
        unsigned long long e, int j, bool asc, int lane) {
    unsigned long long p = __shfl_xor_sync(0xFFFFFFFFu, e, j);
    bool low = ((lane & j) == 0);
    bool keepmin = (low == asc);
    unsigned long long mn = (e < p) ? e : p;
    unsigned long long mx = (e < p) ? p : e;
    return keepmin ? mn : mx;
}

__global__ __launch_bounds__(1024, 1)
void sortdec_kernel(const float* __restrict__ cls,
                    const float* __restrict__ reg,
                    const float* __restrict__ anc) {
    extern __shared__ char dsm[];                                  // 64KB
    unsigned* hist = reinterpret_cast<unsigned*>(dsm);             // 16x1024 u32
    unsigned long long* sb = reinterpret_cast<unsigned long long*>(dsm); // alias 16KB
    __shared__ unsigned s_totals[16];
    __shared__ float s_blo;
    __shared__ int s_above, s_cand, s_cnt;

    const int c = blockIdx.x;
    const int tid = threadIdx.x, lane = tid & 31, wid = tid >> 5;

    int cnt = g_cnt[c];
    bool fast = (cnt >= KK && cnt <= CAP);

    if (fast) {
        sb[tid]        = (tid < cnt)        ? g_cand[c * CAP + tid]        : ~0ull;
        sb[tid + 1024] = (tid + 1024 < cnt) ? g_cand[c * CAP + tid + 1024] : ~0ull;
        __syncthreads();
    } else {
        // ---- exact slow path: 16-way hierarchical refine on strided column
        float blo = 0.0f, bwid = 1.0f / 16.0f;
        int aboveCnt = 0, candTotal = AN;
        for (int level = 0; level < 4; ++level) {
#pragma unroll
            for (int b = 0; b < 16; ++b) hist[b * 1024 + tid] = 0;
            __syncthreads();
            const float inv = 1.0f / bwid;
            for (int a = tid; a < AN; a += 1024) {
                float x = cls[(size_t)a * NC + c];
                if (level == 0) {
                    int b = (int)(x * 16.0f);
                    b = b < 0 ? 0 : (b > 15 ? 15 : b);
                    hist[b * 1024 + tid] += 1u;
                } else {
                    float t = (x - blo) * inv;
                    if (x >= blo && t < 16.0f)
                        hist[(int)t * 1024 + tid] += 1u;
                }
            }
            __syncthreads();
            if (wid < 16) {
                unsigned s = 0;
#pragma unroll
                for (int k = 0; k < 32; ++k) s += hist[wid * 1024 + k * 32 + lane];
#pragma unroll
                for (int o = 16; o > 0; o >>= 1) s += __shfl_down_sync(0xFFFFFFFFu, s, o);
                if (lane == 0) s_totals[wid] = s;
            }
            __syncthreads();
            if (tid == 0) {
                int cum = aboveCnt, b = 15;
                for (; b >= 0; --b) { cum += (int)s_totals[b]; if (cum >= KK) break; }
                if (b < 0) b = 0;
                s_blo = blo + (float)b * bwid;
                s_above = cum - (int)s_totals[b];
                s_cand = cum;
            }
            __syncthreads();
            blo = s_blo; aboveCnt = s_above; candTotal = s_cand;
            bwid *= (1.0f / 16.0f);
            __syncthreads();
            if (candTotal <= 1800) break;
        }
        const float thr = blo - bwid;
        if (tid == 0) s_cnt = 0;
        __syncthreads();
        for (int a = tid; a < AN; a += 1024) {
            float x = cls[(size_t)a * NC + c];
            if (x >= thr) {
                int p = atomicAdd(&s_cnt, 1);
                if (p < CAP)
                    sb[p] = ((unsigned long long)(~order_key(x)) << 32) | (unsigned)a;
            }
        }
        __syncthreads();
        int cn = s_cnt; if (cn > CAP) cn = CAP;
        for (int i = cn + tid; i < CAP; i += 1024) sb[i] = ~0ull;
        __syncthreads();
    }

    // ---- hybrid bitonic sort 2048 (asc u64 = score desc, idx asc) ----
    unsigned long long e0 = sb[64 * wid + lane];
    unsigned long long e1 = sb[64 * wid + 32 + lane];
#pragma unroll
    for (int k2 = 2; k2 <= 16; k2 <<= 1) {
#pragma unroll
        for (int j = k2 >> 1; j >= 1; j >>= 1) {
            bool a0 = ((lane & k2) == 0);
            e0 = bx_exch(e0, j, a0, lane);
            e1 = bx_exch(e1, j, a0, lane);
        }
    }
#pragma unroll
    for (int j = 16; j >= 1; j >>= 1) {
        e0 = bx_exch(e0, j, true, lane);
        e1 = bx_exch(e1, j, false, lane);
    }
    {
        bool A = ((wid & 1) == 0);
        unsigned long long mn = (e0 < e1) ? e0 : e1;
        unsigned long long mx = (e0 < e1) ? e1 : e0;
        e0 = A ? mn : mx; e1 = A ? mx : mn;
#pragma unroll
        for (int j = 16; j >= 1; j >>= 1) {
            e0 = bx_exch(e0, j, A, lane);
            e1 = bx_exch(e1, j, A, lane);
        }
    }
    for (int k2 = 128; k2 <= CAP; k2 <<= 1) {
        sb[64 * wid + lane] = e0;
        sb[64 * wid + 32 + lane] = e1;
        __syncthreads();
        for (int j = k2 >> 1; j >= 64; j >>= 1) {
            int i1 = ((tid & ~(j - 1)) << 1) | (tid & (j - 1));
            int i2 = i1 | j;
            unsigned long long a = sb[i1];
            unsigned long long b = sb[i2];
            bool asc = ((i1 & k2) == 0);
            if ((a > b) == asc) { sb[i1] = b; sb[i2] = a; }
            __syncthreads();
        }
        e0 = sb[64 * wid + lane];
        e1 = sb[64 * wid + 32 + lane];
        bool A = (((wid * 64) & k2) == 0);
        unsigned long long mn = (e0 < e1) ? e0 : e1;
        unsigned long long mx = (e0 < e1) ? e1 : e0;
        e0 = A ? mn : mx; e1 = A ? mx : mn;
#pragma unroll
        for (int j = 16; j >= 1; j >>= 1) {
            e0 = bx_exch(e0, j, A, lane);
            e1 = bx_exch(e1, j, A, lane);
        }
    }
    sb[64 * wid + lane] = e0;
    sb[64 * wid + 32 + lane] = e1;
    __syncthreads();

    // ---- decode + clip -> global scratch ----
    float sc = 0.0f;
    if (tid < KK) {
        unsigned long long kv = sb[tid];
        if (kv != ~0ull) {
            unsigned kk = ~(unsigned)(kv >> 32);
            unsigned u = (kk & 0x80000000u) ? (kk ^ 0x80000000u) : ~kk;
            sc = __uint_as_float(u);
            int idx = (int)(kv & 0xFFFFFFFFull);
            float4 a = reinterpret_cast<const float4*>(anc)[idx];
            float4 r = reinterpret_cast<const float4*>(reg)[idx];
            float wa = a.z - a.x, ha = a.w - a.y;
            float cxa = a.x + 0.5f * wa, cya = a.y + 0.5f * ha;
            float cx = cxa + (r.x * 0.1f) * wa;
            float cy = cya + (r.y * 0.1f) * ha;
            float w = __expf(r.z * 0.2f) * wa;
            float h = __expf(r.w * 0.2f) * ha;
            float4 b;
            b.x = fminf(fmaxf(cx - 0.5f * w, 0.0f), 1024.0f);
            b.y = fminf(fmaxf(cy - 0.5f * h, 0.0f), 1024.0f);
            b.z = fminf(fmaxf(cx + 0.5f * w, 0.0f), 1024.0f);
            b.w = fminf(fmaxf(cy + 0.5f * h, 0.0f), 1024.0f);
            g_box[c * 1024 + tid] = b;
            g_score[c * 1024 + tid] = sc;
        } else {
            g_box[c * 1024 + tid] = make_float4(0.f, 0.f, 0.f, 0.f);
            g_score[c * 1024 + tid] = 0.0f;
        }
    } else {
        g_box[c * 1024 + tid] = make_float4(0.f, 0.f, 0.f, 0.f);
        g_score[c * 1024 + tid] = 0.0f;
    }
    unsigned bal = __ballot_sync(0xFFFFFFFFu, (tid < KK) && (sc > 0.05f));
    if (lane == 0) g_vb[c * 32 + wid] = bal;
}

// ---------------------------------------------------------------------------
// K3: NMS bitmask build — 512 threads, 96 warps/class, strided triangle tasks
// ---------------------------------------------------------------------------
__global__ __launch_bounds__(512) void mask_kernel() {
    __shared__ float4 sbox[1024];
    __shared__ float  sar[1024];
    const int c = blockIdx.y, p = blockIdx.x;
    const int tid = threadIdx.x, lane = tid & 31, wid = tid >> 5;

    for (int i = tid; i < 1024; i += 512) {
        float4 b = g_box[c * 1024 + i];
        sbox[i] = b;
        sar[i] = (b.z - b.x) * (b.w - b.y);
    }
    __syncthreads();

    const int gw = p * 16 + wid;    // 0..95
    for (int t = gw; t < 528; t += MPARTS * 16) {
        int bi = 0, rem = t;
        while (rem >= 32 - bi) { rem -= 32 - bi; ++bi; }
        int bj = bi + rem;

        float4 br = sbox[bi * 32 + lane];
        float arE = sar[bi * 32 + lane] + 1e-8f;
        unsigned bits = 0;
#pragma unroll
        for (int jj = 0; jj < 32; ++jj) {
            float4 bc = sbox[bj * 32 + jj];     // broadcast
            float ac = sar[bj * 32 + jj];
            float w = fminf(br.z, bc.z) - fmaxf(br.x, bc.x);
            float h = fminf(br.w, bc.w) - fmaxf(br.y, bc.y);
            float inter = fmaxf(w, 0.0f) * fmaxf(h, 0.0f);
            bool pr = (fmaf(inter, 3.0f, -(arE + ac)) > 0.0f);   // iou > 0.5
            bits |= pr ? (1u << jj) : 0u;
        }
        if (bi == bj) {
            bits &= (0xFFFFFFFEu << lane);         // only jj > lane
            g_diag[c * 1024 + bi * 32 + lane] = bits;
        }
        g_maskT[(c * 32 + bj) * 1024 + bi * 32 + lane] = bits;  // coalesced
    }
}

// ---------------------------------------------------------------------------
// K4: serial greedy reduce + outputs, grid NC
// ---------------------------------------------------------------------------
__global__ __launch_bounds__(1024, 1) void reduce_kernel(float* __restrict__ out) {
    extern __shared__ unsigned smT[];     // [32 wordcols][1025 rows-padded]
    __shared__ unsigned s_diag[1024];
    __shared__ unsigned s_vb[32];
    __shared__ unsigned s_rm[32];
    const int c = blockIdx.x, tid = threadIdx.x, lane = tid & 31, wid = tid >> 5;

    const uint4* gm4 = reinterpret_cast<const uint4*>(g_maskT + c * 32768);
    int wq = tid & 3;
    int r4 = tid >> 2;
    int rb = r4 >> 3;
#pragma unroll
    for (int k = 0; k < 8; ++k) {
        int wcol = k * 4 + wq;
        uint4 v = gm4[wcol * 256 + r4];
        if (wcol < rb) v = make_uint4(0u, 0u, 0u, 0u);
        unsigned* d = &smT[wcol * 1025 + r4 * 4];
        d[0] = v.x; d[1] = v.y; d[2] = v.z; d[3] = v.w;
    }
    s_diag[tid] = g_diag[c * 1024 + tid];
    if (tid < 32) s_vb[tid] = g_vb[c * 32 + tid];
    __syncthreads();

    if (wid == 0) {
        unsigned removed = 0;
        unsigned vbl = s_vb[lane];
        for (int b = 0; b < 32; ++b) {
            unsigned rmw = __shfl_sync(0xFFFFFFFFu, removed, b);
            unsigned vbw = __shfl_sync(0xFFFFFFFFu, vbl, b);
#pragma unroll
            for (int r = 0; r < 32; ++r) {
                unsigned dgr = s_diag[b * 32 + r];
                unsigned mrr = smT[lane * 1025 + b * 32 + r];
                bool kept = ((vbw >> r) & 1u) && !((rmw >> r) & 1u);
                if (kept) { rmw |= dgr; removed |= mrr; }
            }
        }
        s_rm[lane] = removed;
    }
    __syncthreads();

    if (tid < KK) {
        int o = c * KK + tid;
        unsigned rw = s_rm[tid >> 5];
        unsigned vb = s_vb[tid >> 5];
        bool kp = ((vb >> (tid & 31)) & 1u) && !((rw >> (tid & 31)) & 1u);
        float sc = g_score[c * 1024 + tid];
        float4 bb = g_box[c * 1024 + tid];
        out[o] = kp ? sc : 0.0f;
        out[NC * KK + o] = kp ? (float)c : -1.0f;
        reinterpret_cast<float4*>(out + 2 * NC * KK)[o] =
            kp ? bb : make_float4(0.f, 0.f, 0.f, 0.f);
        out[6 * NC * KK + o] = kp ? 1.0f : 0.0f;
    }
}

// ---------------------------------------------------------------------------
extern "C" void kernel_launch(void* const* d_in, const int* in_sizes, int n_in,
                              void* d_out, int out_size) {
    const float* cls = (const float*)d_in[0];
    const float* reg = (const float*)d_in[1];
    const float* anc = (const float*)d_in[2];
    float* out = (float*)d_out;

    init_kernel<<<1, 128>>>();

    collect_kernel<<<COLGRID, 256>>>(cls);

    int selSmem = 16 * 1024 * 4;   // 64KB
    cudaFuncSetAttribute(sortdec_kernel,
                         cudaFuncAttributeMaxDynamicSharedMemorySize, selSmem);
    sortdec_kernel<<<NC, 1024, selSmem>>>(cls, reg, anc);

    mask_kernel<<<dim3(MPARTS, NC), 512>>>();

    int redSmem = 32 * 1025 * 4;
    cudaFuncSetAttribute(reduce_kernel,
                         cudaFuncAttributeMaxDynamicSharedMemorySize, redSmem);
    reduce_kernel<<<NC, 1024, redSmem>>>(out);
}

// round 16
// speedup vs baseline: 1.4957x; 1.4957x over previous
#include <cuda_runtime.h>
#include <math.h>
#include <stdint.h>

#define MAXC 128
#define KP 1024
#define CAP 2048
#define PARTS 11
#define COLGRID 1184
#define T0 (254.0f / 256.0f)

// ---------------- global scratch ----------------
__device__ int                g_cnt[MAXC];
__device__ int                g_swap;
__device__ unsigned long long g_cand[MAXC * CAP];
__device__ float4             g_box  [MAXC * KP];
__device__ float              g_score[MAXC * KP];
__device__ unsigned           g_vb   [MAXC * 32];
__device__ unsigned           g_maskT[MAXC * 32 * KP];   // [class][wordcol][row]
__device__ unsigned           g_diag [MAXC * KP];

__device__ __forceinline__ unsigned order_key(float x) {
    unsigned u = __float_as_uint(x);
    return (u & 0x80000000u) ? ~u : (u | 0x80000000u);
}

// ---------------------------------------------------------------------------
// K0: zero counters + detect which [A,4] input is anchors (x2-x1 > 1 always)
// ---------------------------------------------------------------------------
__global__ void initz_v4(const float* __restrict__ rc, const float* __restrict__ ac) {
    if (threadIdx.x < MAXC) g_cnt[threadIdx.x] = 0;
    if (threadIdx.x == 0) {
        bool rcAnch = true, acAnch = true;
        for (int k = 0; k < 8; ++k) {
            rcAnch = rcAnch && ((rc[k * 4 + 2] - rc[k * 4 + 0]) > 1.0f);
            acAnch = acAnch && ((ac[k * 4 + 2] - ac[k * 4 + 0]) > 1.0f);
        }
        // swap if the "regression" candidate looks like anchors and the other doesn't
        g_swap = (rcAnch && !acAnch) ? 1 : 0;
    }
}

// ---------------------------------------------------------------------------
// K1: chip-wide candidate collect from [A, C] layout (runtime dims)
// ---------------------------------------------------------------------------
__global__ __launch_bounds__(256) void collect_v4(const float* __restrict__ cls,
                                                  int A, int C) {
    if ((C & 3) == 0) {
        const float4* __restrict__ p4 = reinterpret_cast<const float4*>(cls);
        int tot4 = (A * C) >> 2;
        for (int i = blockIdx.x * 256 + threadIdx.x; i < tot4; i += COLGRID * 256) {
            float4 v = p4[i];
            if (v.x >= T0 || v.y >= T0 || v.z >= T0 || v.w >= T0) {
                int f = i * 4;
                int a = f / C;
                int c0 = f - a * C;
#define PUSH(x, k)                                                            \
                if ((x) >= T0) {                                              \
                    int cc = c0 + (k);                                        \
                    int pos = atomicAdd(&g_cnt[cc], 1);                       \
                    if (pos < CAP)                                            \
                        g_cand[cc * CAP + pos] =                              \
                            ((unsigned long long)(~order_key(x)) << 32)       \
                            | (unsigned)a;                                    \
                }
                PUSH(v.x, 0) PUSH(v.y, 1) PUSH(v.z, 2) PUSH(v.w, 3)
#undef PUSH
            }
        }
    } else {
        int tot = A * C;
        for (int i = blockIdx.x * 256 + threadIdx.x; i < tot; i += COLGRID * 256) {
            float x = cls[i];
            if (x >= T0) {
                int a = i / C;
                int cc = i - a * C;
                int pos = atomicAdd(&g_cnt[cc], 1);
                if (pos < CAP)
                    g_cand[cc * CAP + pos] =
                        ((unsigned long long)(~order_key(x)) << 32) | (unsigned)a;
            }
        }
    }
}

// ---------------------------------------------------------------------------
// K2: per-class top-K select + sort + decode (runtime A, C, K)
// ---------------------------------------------------------------------------
__device__ __forceinline__ unsigned long long bx_exch(
        unsigned long long e, int j, bool asc, int lane) {
    unsigned long long p = __shfl_xor_sync(0xFFFFFFFFu, e, j);
    bool low = ((lane & j) == 0);
    bool keepmin = (low == asc);
    unsigned long long mn = (e < p) ? e : p;
    unsigned long long mx = (e < p) ? p : e;
    return keepmin ? mn : mx;
}

__global__ __launch_bounds__(1024, 1)
void seldec_v4(const float* __restrict__ cls,
               const float* __restrict__ regc,
               const float* __restrict__ ancc,
               int A, int C, int K) {
    extern __shared__ char dsm[];                                  // 64KB
    unsigned* hist = reinterpret_cast<unsigned*>(dsm);
    unsigned long long* sb = reinterpret_cast<unsigned long long*>(dsm);
    __shared__ unsigned s_totals[16];
    __shared__ int s_above, s_cand, s_bin, s_cnt, s_fill;
    __shared__ int s_wsum[32];

    const int c = blockIdx.x;
    const int tid = threadIdx.x, lane = tid & 31, wid = tid >> 5;
    const unsigned lt = (1u << lane) - 1u;

    const float* __restrict__ reg = g_swap ? ancc : regc;
    const float* __restrict__ anc = g_swap ? regc : ancc;

    int cnt = g_cnt[c];
    bool fast = (cnt >= K && cnt <= CAP);

    if (fast) {
        sb[tid]        = (tid < cnt)        ? g_cand[c * CAP + tid]        : ~0ull;
        sb[tid + 1024] = (tid + 1024 < cnt) ? g_cand[c * CAP + tid + 1024] : ~0ull;
        __syncthreads();
    } else {
        // ---- exact bitwise radix select on order_key (any distribution) ----
        unsigned prefix = 0, pmask = 0;
        int aboveCnt = 0, candTotal = A;
        bool resolved = false;
        for (int shift = 28; shift >= 0; shift -= 4) {
#pragma unroll
            for (int b = 0; b < 16; ++b) hist[b * 1024 + tid] = 0;
            __syncthreads();
            for (int a = tid; a < A; a += 1024) {
                unsigned k = order_key(cls[(size_t)a * C + c]);
                if ((k & pmask) == prefix)
                    hist[((k >> shift) & 15) * 1024 + tid] += 1u;
            }
            __syncthreads();
            if (wid < 16) {
                unsigned s = 0;
#pragma unroll
                for (int k = 0; k < 32; ++k) s += hist[wid * 1024 + k * 32 + lane];
#pragma unroll
                for (int o = 16; o > 0; o >>= 1) s += __shfl_down_sync(0xFFFFFFFFu, s, o);
                if (lane == 0) s_totals[wid] = s;
            }
            __syncthreads();
            if (tid == 0) {
                int cum = aboveCnt, b = 15;
                for (; b >= 0; --b) { cum += (int)s_totals[b]; if (cum >= K) break; }
                if (b < 0) b = 0;
                s_above = cum - (int)s_totals[b];
                s_cand = cum;
                s_bin = b;
            }
            __syncthreads();
            aboveCnt = s_above; candTotal = s_cand;
            prefix |= ((unsigned)s_bin) << shift;
            pmask  |= 0xFu << shift;
            __syncthreads();
            if (candTotal <= CAP) { resolved = true; break; }
        }
        const unsigned T = prefix;

        if (resolved) {
            if (tid == 0) s_cnt = 0;
            __syncthreads();
            for (int a = tid; a < A; a += 1024) {
                unsigned k = order_key(cls[(size_t)a * C + c]);
                if (k >= T) {
                    int p = atomicAdd(&s_cnt, 1);
                    if (p < CAP)
                        sb[p] = ((unsigned long long)(~k) << 32) | (unsigned)a;
                }
            }
            __syncthreads();
            int cn = s_cnt; if (cn > CAP) cn = CAP;
            for (int i = cn + tid; i < CAP; i += 1024) sb[i] = ~0ull;
            __syncthreads();
        } else {
            if (tid == 0) { s_cnt = 0; s_fill = 0; }
            __syncthreads();
            for (int a = tid; a < A; a += 1024) {
                unsigned k = order_key(cls[(size_t)a * C + c]);
                if (k > T) {
                    int p = atomicAdd(&s_cnt, 1);
                    if (p < CAP)
                        sb[p] = ((unsigned long long)(~k) << 32) | (unsigned)a;
                }
            }
            __syncthreads();
            const int base = s_cnt;
            const int needTies = K - base;
            for (int basei = 0; basei < A; basei += 1024) {
                if (s_fill >= needTies) break;
                int a = basei + tid;
                bool p = false;
                if (a < A) p = (order_key(cls[(size_t)a * C + c]) == T);
                unsigned m = __ballot_sync(0xFFFFFFFFu, p);
                if (lane == 0) s_wsum[wid] = __popc(m);
                __syncthreads();
                if (tid < 32) {
                    int v = s_wsum[tid];
#pragma unroll
                    for (int o = 1; o < 32; o <<= 1) {
                        int t = __shfl_up_sync(0xFFFFFFFFu, v, o);
                        if (tid >= o) v += t;
                    }
                    s_wsum[tid] = v;
                }
                __syncthreads();
                int wbase = wid ? s_wsum[wid - 1] : 0;
                int rank = s_fill + wbase + __popc(m & lt);
                if (p && rank < needTies)
                    sb[base + rank] = ((unsigned long long)(~T) << 32) | (unsigned)a;
                __syncthreads();
                if (tid == 0) s_fill += s_wsum[31];
                __syncthreads();
            }
            for (int i = K + tid; i < CAP; i += 1024) sb[i] = ~0ull;
            __syncthreads();
        }
    }

    // ---- hybrid bitonic sort 2048 (asc u64 = score desc, idx asc) ----
    unsigned long long e0 = sb[64 * wid + lane];
    unsigned long long e1 = sb[64 * wid + 32 + lane];
#pragma unroll
    for (int k2 = 2; k2 <= 16; k2 <<= 1) {
#pragma unroll
        for (int j = k2 >> 1; j >= 1; j >>= 1) {
            bool a0 = ((lane & k2) == 0);
            e0 = bx_exch(e0, j, a0, lane);
            e1 = bx_exch(e1, j, a0, lane);
        }
    }
#pragma unroll
    for (int j = 16; j >= 1; j >>= 1) {
        e0 = bx_exch(e0, j, true, lane);
        e1 = bx_exch(e1, j, false, lane);
    }
    {
        bool Aa = ((wid & 1) == 0);
        unsigned long long mn = (e0 < e1) ? e0 : e1;
        unsigned long long mx = (e0 < e1) ? e1 : e0;
        e0 = Aa ? mn : mx; e1 = Aa ? mx : mn;
#pragma unroll
        for (int j = 16; j >= 1; j >>= 1) {
            e0 = bx_exch(e0, j, Aa, lane);
            e1 = bx_exch(e1, j, Aa, lane);
        }
    }
    for (int k2 = 128; k2 <= CAP; k2 <<= 1) {
        sb[64 * wid + lane] = e0;
        sb[64 * wid + 32 + lane] = e1;
        __syncthreads();
        for (int j = k2 >> 1; j >= 64; j >>= 1) {
            int i1 = ((tid & ~(j - 1)) << 1) | (tid & (j - 1));
            int i2 = i1 | j;
            unsigned long long a = sb[i1];
            unsigned long long b = sb[i2];
            bool asc = ((i1 & k2) == 0);
            if ((a > b) == asc) { sb[i1] = b; sb[i2] = a; }
            __syncthreads();
        }
        e0 = sb[64 * wid + lane];
        e1 = sb[64 * wid + 32 + lane];
        bool Aa = (((wid * 64) & k2) == 0);
        unsigned long long mn = (e0 < e1) ? e0 : e1;
        unsigned long long mx = (e0 < e1) ? e1 : e0;
        e0 = Aa ? mn : mx; e1 = Aa ? mx : mn;
#pragma unroll
        for (int j = 16; j >= 1; j >>= 1) {
            e0 = bx_exch(e0, j, Aa, lane);
            e1 = bx_exch(e1, j, Aa, lane);
        }
    }
    sb[64 * wid + lane] = e0;
    sb[64 * wid + 32 + lane] = e1;
    __syncthreads();

    // ---- decode + clip -> global scratch ----
    float sc = 0.0f;
    if (tid < K) {
        unsigned long long kv = sb[tid];
        if (kv != ~0ull) {
            unsigned kk = ~(unsigned)(kv >> 32);
            unsigned u = (kk & 0x80000000u) ? (kk ^ 0x80000000u) : ~kk;
            sc = __uint_as_float(u);
            int idx = (int)(kv & 0xFFFFFFFFull);
            float4 a = reinterpret_cast<const float4*>(anc)[idx];
            float4 r = reinterpret_cast<const float4*>(reg)[idx];
            float wa = a.z - a.x, ha = a.w - a.y;
            float cxa = a.x + 0.5f * wa, cya = a.y + 0.5f * ha;
            float cx = cxa + (r.x * 0.1f) * wa;
            float cy = cya + (r.y * 0.1f) * ha;
            float w = expf(r.z * 0.2f) * wa;
            float h = expf(r.w * 0.2f) * ha;
            float4 b;
            b.x = fminf(fmaxf(cx - 0.5f * w, 0.0f), 1024.0f);
            b.y = fminf(fmaxf(cy - 0.5f * h, 0.0f), 1024.0f);
            b.z = fminf(fmaxf(cx + 0.5f * w, 0.0f), 1024.0f);
            b.w = fminf(fmaxf(cy + 0.5f * h, 0.0f), 1024.0f);
            g_box[c * KP + tid] = b;
            g_score[c * KP + tid] = sc;
        } else {
            g_box[c * KP + tid] = make_float4(0.f, 0.f, 0.f, 0.f);
            g_score[c * KP + tid] = 0.0f;
        }
    } else {
        g_box[c * KP + tid] = make_float4(0.f, 0.f, 0.f, 0.f);
        g_score[c * KP + tid] = 0.0f;
    }
    unsigned bal = __ballot_sync(0xFFFFFFFFu, (tid < K) && (sc > 0.05f));
    if (lane == 0) g_vb[c * 32 + wid] = bal;
}

// ---------------------------------------------------------------------------
// K3: NMS bitmask build (R7-proven inner loop)
// ---------------------------------------------------------------------------
__global__ __launch_bounds__(256, 1) void maskb_v4() {
    __shared__ float4 sbox[KP];
    __shared__ float  sar[KP];
    const int c = blockIdx.y, p = blockIdx.x;
    const int tid = threadIdx.x, lane = tid & 31, wid = tid >> 5;

    for (int i = tid; i < KP; i += 256) {
        float4 b = g_box[c * KP + i];
        sbox[i] = b;
        sar[i] = (b.z - b.x) * (b.w - b.y);
    }
    __syncthreads();

    int gw = p * 8 + wid;          // 0..87 ; 88 * 6 = 528 tasks
    int t0 = gw * 6;
    int bi = 0, rem = t0;
    while (rem >= 32 - bi) { rem -= 32 - bi; ++bi; }
    int bj = bi + rem;

    for (int s = 0; s < 6; ++s) {
        float4 br = sbox[bi * 32 + lane];
        float arE = sar[bi * 32 + lane] + 1e-8f;
        unsigned bits = 0;
#pragma unroll
        for (int jj = 0; jj < 32; ++jj) {
            float4 bc = sbox[bj * 32 + jj];     // broadcast
            float ac = sar[bj * 32 + jj];
            float w = fminf(br.z, bc.z) - fmaxf(br.x, bc.x);
            float h = fminf(br.w, bc.w) - fmaxf(br.y, bc.y);
            float inter = fmaxf(w, 0.0f) * fmaxf(h, 0.0f);
            bool pr = (inter * 3.0f > arE + ac);   // iou > 0.5
            bits |= pr ? (1u << jj) : 0u;
        }
        if (bi == bj) {
            bits &= (0xFFFFFFFEu << lane);         // only jj > lane
            g_diag[c * KP + bi * 32 + lane] = bits;
        }
        g_maskT[(c * 32 + bj) * KP + bi * 32 + lane] = bits;  // coalesced
        if (++bj == 32) { ++bi; bj = bi; }
    }
}

// ---------------------------------------------------------------------------
// K4: serial greedy reduce + outputs (runtime C, K offsets)
// ---------------------------------------------------------------------------
__global__ __launch_bounds__(1024, 1) void reduceo_v4(float* __restrict__ out,
                                                      int C, int K) {
    extern __shared__ unsigned smT[];     // [32 wordcols][1025 rows-padded]
    __shared__ unsigned s_diag[KP];
    __shared__ unsigned s_vb[32];
    __shared__ unsigned s_rm[32];
    const int c = blockIdx.x, tid = threadIdx.x, lane = tid & 31, wid = tid >> 5;

    const uint4* gm4 = reinterpret_cast<const uint4*>(g_maskT + c * 32 * KP);
    int wq = tid & 3;
    int r4 = tid >> 2;
    int rb = r4 >> 3;
#pragma unroll
    for (int k = 0; k < 8; ++k) {
        int wcol = k * 4 + wq;
        uint4 v = gm4[wcol * 256 + r4];
        if (wcol < rb) v = make_uint4(0u, 0u, 0u, 0u);
        unsigned* d = &smT[wcol * 1025 + r4 * 4];
        d[0] = v.x; d[1] = v.y; d[2] = v.z; d[3] = v.w;
    }
    s_diag[tid] = g_diag[c * KP + tid];
    if (tid < 32) s_vb[tid] = g_vb[c * 32 + tid];
    __syncthreads();

    if (wid == 0) {
        unsigned removed = 0;
        unsigned vbl = s_vb[lane];
        for (int b = 0; b < 32; ++b) {
            unsigned rmw = __shfl_sync(0xFFFFFFFFu, removed, b);
            unsigned vbw = __shfl_sync(0xFFFFFFFFu, vbl, b);
#pragma unroll
            for (int r = 0; r < 32; ++r) {
                unsigned dgr = s_diag[b * 32 + r];
                unsigned mrr = smT[lane * 1025 + b * 32 + r];
                bool kept = ((vbw >> r) & 1u) && !((rmw >> r) & 1u);
                if (kept) { rmw |= dgr; removed |= mrr; }
            }
        }
        s_rm[lane] = removed;
    }
    __syncthreads();

    if (tid < K) {
        int o = c * K + tid;
        unsigned rw = s_rm[tid >> 5];
        unsigned vb = s_vb[tid >> 5];
        bool kp = ((vb >> (tid & 31)) & 1u) && !((rw >> (tid & 31)) & 1u);
        float sc = g_score[c * KP + tid];
        float4 bb = g_box[c * KP + tid];
        int CK = C * K;
        out[o] = kp ? sc : 0.0f;                                  // scores
        out[CK + o] = kp ? (float)c : -1.0f;                      // labels
        float4 zb = make_float4(0.f, 0.f, 0.f, 0.f);
        float4 ob = kp ? bb : zb;
        out[2 * CK + 4 * o + 0] = ob.x;                           // boxes
        out[2 * CK + 4 * o + 1] = ob.y;
        out[2 * CK + 4 * o + 2] = ob.z;
        out[2 * CK + 4 * o + 3] = ob.w;
        out[6 * CK + o] = kp ? 1.0f : 0.0f;                       // keep
    }
}

// ---------------------------------------------------------------------------
extern "C" void kernel_launch(void* const* d_in, const int* in_sizes, int n_in,
                              void* d_out, int out_size) {
    // identify classification = largest input
    int cidx = 0;
    for (int i = 1; i < n_in; ++i)
        if (in_sizes[i] > in_sizes[cidx]) cidx = i;
    int o1 = -1, o2 = -1;
    for (int i = 0; i < n_in; ++i)
        if (i != cidx) { if (o1 < 0) o1 = i; else o2 = i; }

    long long A = in_sizes[o1] / 4;
    if (A < 1) A = 1;
    int C = (int)(in_sizes[cidx] / A);
    if (C < 1) C = 1;
    if (C > MAXC) C = MAXC;
    int K = (out_size > 0 && C > 0) ? out_size / (7 * C) : 1000;
    if (K < 1 || K > KP) K = 1000;

    const float* cls = (const float*)d_in[cidx];
    const float* rc  = (const float*)d_in[o1];   // regression candidate
    const float* ac  = (const float*)d_in[o2];   // anchors candidate
    float* out = (float*)d_out;

    initz_v4<<<1, 128>>>(rc, ac);

    collect_v4<<<COLGRID, 256>>>(cls, (int)A, C);

    int selSmem = 16 * 1024 * 4;   // 64KB
    cudaFuncSetAttribute(seldec_v4,
                         cudaFuncAttributeMaxDynamicSharedMemorySize, selSmem);
    seldec_v4<<<C, 1024, selSmem>>>(cls, rc, ac, (int)A, C, K);

    maskb_v4<<<dim3(PARTS, C), 256>>>();

    int redSmem = 32 * 1025 * 4;
    cudaFuncSetAttribute(reduceo_v4,
                         cudaFuncAttributeMaxDynamicSharedMemorySize, redSmem);
    reduceo_v4<<<C, 1024, redSmem>>>(out, C, K);
}

// round 17
// speedup vs baseline: 1.5205x; 1.0166x over previous
#include <cuda_runtime.h>
#include <math.h>
#include <stdint.h>

#define MAXC 128
#define KP 1024
#define CAP 2048
#define PARTS 11
#define COLGRID 1184
#define T0 (254.0f / 256.0f)

// ---------------- global scratch ----------------
__device__ int                g_cnt[MAXC];
__device__ int                g_swap;
__device__ unsigned long long g_cand[MAXC * CAP];
__device__ float4             g_box  [MAXC * KP];
__device__ float              g_score[MAXC * KP];
__device__ unsigned           g_vb   [MAXC * 32];
__device__ unsigned           g_maskT[MAXC * 32 * KP];   // [class][wordcol][row]
__device__ unsigned           g_diag [MAXC * KP];

__device__ __forceinline__ unsigned order_key(float x) {
    unsigned u = __float_as_uint(x);
    return (u & 0x80000000u) ? ~u : (u | 0x80000000u);
}

// ---------------------------------------------------------------------------
// K0: zero counters + detect which [A,4] input is anchors (x2-x1 > 1 always)
// ---------------------------------------------------------------------------
__global__ void initz_v5(const float* __restrict__ rc, const float* __restrict__ ac) {
    if (threadIdx.x < MAXC) g_cnt[threadIdx.x] = 0;
    if (threadIdx.x == 0) {
        bool rcAnch = true, acAnch = true;
        for (int k = 0; k < 8; ++k) {
            rcAnch = rcAnch && ((rc[k * 4 + 2] - rc[k * 4 + 0]) > 1.0f);
            acAnch = acAnch && ((ac[k * 4 + 2] - ac[k * 4 + 0]) > 1.0f);
        }
        g_swap = (rcAnch && !acAnch) ? 1 : 0;
    }
}

// ---------------------------------------------------------------------------
// K1: chip-wide candidate collect from [A, C] layout (runtime dims)
// ---------------------------------------------------------------------------
__global__ __launch_bounds__(256) void collect_v5(const float* __restrict__ cls,
                                                  int A, int C) {
    if ((C & 3) == 0) {
        const float4* __restrict__ p4 = reinterpret_cast<const float4*>(cls);
        int tot4 = (A * C) >> 2;
        for (int i = blockIdx.x * 256 + threadIdx.x; i < tot4; i += COLGRID * 256) {
            float4 v = p4[i];
            if (v.x >= T0 || v.y >= T0 || v.z >= T0 || v.w >= T0) {
                int f = i * 4;
                int a = f / C;
                int c0 = f - a * C;
#define PUSH(x, k)                                                            \
                if ((x) >= T0) {                                              \
                    int cc = c0 + (k);                                        \
                    int pos = atomicAdd(&g_cnt[cc], 1);                       \
                    if (pos < CAP)                                            \
                        g_cand[cc * CAP + pos] =                              \
                            ((unsigned long long)(~order_key(x)) << 32)       \
                            | (unsigned)a;                                    \
                }
                PUSH(v.x, 0) PUSH(v.y, 1) PUSH(v.z, 2) PUSH(v.w, 3)
#undef PUSH
            }
        }
    } else {
        int tot = A * C;
        for (int i = blockIdx.x * 256 + threadIdx.x; i < tot; i += COLGRID * 256) {
            float x = cls[i];
            if (x >= T0) {
                int a = i / C;
                int cc = i - a * C;
                int pos = atomicAdd(&g_cnt[cc], 1);
                if (pos < CAP)
                    g_cand[cc * CAP + pos] =
                        ((unsigned long long)(~order_key(x)) << 32) | (unsigned)a;
            }
        }
    }
}

// ---------------------------------------------------------------------------
// K2: per-class top-K select + sort + decode (runtime A, C, K)
// ---------------------------------------------------------------------------
__device__ __forceinline__ unsigned long long bx_exch(
        unsigned long long e, int j, bool asc, int lane) {
    unsigned long long p = __shfl_xor_sync(0xFFFFFFFFu, e, j);
    bool low = ((lane & j) == 0);
    bool keepmin = (low == asc);
    unsigned long long mn = (e < p) ? e : p;
    unsigned long long mx = (e < p) ? p : e;
    return keepmin ? mn : mx;
}

__global__ __launch_bounds__(1024, 1)
void seldec_v5(const float* __restrict__ cls,
               const float* __restrict__ regc,
               const float* __restrict__ ancc,
               int A, int C, int K) {
    extern __shared__ char dsm[];                                  // 64KB
    unsigned* hist = reinterpret_cast<unsigned*>(dsm);
    unsigned long long* sb = reinterpret_cast<unsigned long long*>(dsm);
    __shared__ unsigned s_totals[16];
    __shared__ int s_above, s_cand, s_bin, s_cnt, s_fill;
    __shared__ int s_wsum[32];

    const int c = blockIdx.x;
    const int tid = threadIdx.x, lane = tid & 31, wid = tid >> 5;
    const unsigned lt = (1u << lane) - 1u;

    const float* __restrict__ reg = g_swap ? ancc : regc;
    const float* __restrict__ anc = g_swap ? regc : ancc;

    int cnt = g_cnt[c];
    bool fast = (cnt >= K && cnt <= CAP);

    if (fast) {
        sb[tid]        = (tid < cnt)        ? g_cand[c * CAP + tid]        : ~0ull;
        sb[tid + 1024] = (tid + 1024 < cnt) ? g_cand[c * CAP + tid + 1024] : ~0ull;
        __syncthreads();
    } else {
        // ---- exact bitwise radix select on order_key (any distribution) ----
        unsigned prefix = 0, pmask = 0;
        int aboveCnt = 0, candTotal = A;
        bool resolved = false;
        for (int shift = 28; shift >= 0; shift -= 4) {
#pragma unroll
            for (int b = 0; b < 16; ++b) hist[b * 1024 + tid] = 0;
            __syncthreads();
            for (int a = tid; a < A; a += 1024) {
                unsigned k = order_key(cls[(size_t)a * C + c]);
                if ((k & pmask) == prefix)
                    hist[((k >> shift) & 15) * 1024 + tid] += 1u;
            }
            __syncthreads();
            if (wid < 16) {
                unsigned s = 0;
#pragma unroll
                for (int k = 0; k < 32; ++k) s += hist[wid * 1024 + k * 32 + lane];
#pragma unroll
                for (int o = 16; o > 0; o >>= 1) s += __shfl_down_sync(0xFFFFFFFFu, s, o);
                if (lane == 0) s_totals[wid] = s;
            }
            __syncthreads();
            if (tid == 0) {
                int cum = aboveCnt, b = 15;
                for (; b >= 0; --b) { cum += (int)s_totals[b]; if (cum >= K) break; }
                if (b < 0) b = 0;
                s_above = cum - (int)s_totals[b];
                s_cand = cum;
                s_bin = b;
            }
            __syncthreads();
            aboveCnt = s_above; candTotal = s_cand;
            prefix |= ((unsigned)s_bin) << shift;
            pmask  |= 0xFu << shift;
            __syncthreads();
            if (candTotal <= CAP) { resolved = true; break; }
        }
        const unsigned T = prefix;

        if (resolved) {
            if (tid == 0) s_cnt = 0;
            __syncthreads();
            for (int a = tid; a < A; a += 1024) {
                unsigned k = order_key(cls[(size_t)a * C + c]);
                if (k >= T) {
                    int p = atomicAdd(&s_cnt, 1);
                    if (p < CAP)
                        sb[p] = ((unsigned long long)(~k) << 32) | (unsigned)a;
                }
            }
            __syncthreads();
            int cn = s_cnt; if (cn > CAP) cn = CAP;
            for (int i = cn + tid; i < CAP; i += 1024) sb[i] = ~0ull;
            __syncthreads();
        } else {
            if (tid == 0) { s_cnt = 0; s_fill = 0; }
            __syncthreads();
            for (int a = tid; a < A; a += 1024) {
                unsigned k = order_key(cls[(size_t)a * C + c]);
                if (k > T) {
                    int p = atomicAdd(&s_cnt, 1);
                    if (p < CAP)
                        sb[p] = ((unsigned long long)(~k) << 32) | (unsigned)a;
                }
            }
            __syncthreads();
            const int base = s_cnt;
            const int needTies = K - base;
            for (int basei = 0; basei < A; basei += 1024) {
                if (s_fill >= needTies) break;
                int a = basei + tid;
                bool p = false;
                if (a < A) p = (order_key(cls[(size_t)a * C + c]) == T);
                unsigned m = __ballot_sync(0xFFFFFFFFu, p);
                if (lane == 0) s_wsum[wid] = __popc(m);
                __syncthreads();
                if (tid < 32) {
                    int v = s_wsum[tid];
#pragma unroll
                    for (int o = 1; o < 32; o <<= 1) {
                        int t = __shfl_up_sync(0xFFFFFFFFu, v, o);
                        if (tid >= o) v += t;
                    }
                    s_wsum[tid] = v;
                }
                __syncthreads();
                int wbase = wid ? s_wsum[wid - 1] : 0;
                int rank = s_fill + wbase + __popc(m & lt);
                if (p && rank < needTies)
                    sb[base + rank] = ((unsigned long long)(~T) << 32) | (unsigned)a;
                __syncthreads();
                if (tid == 0) s_fill += s_wsum[31];
                __syncthreads();
            }
            for (int i = K + tid; i < CAP; i += 1024) sb[i] = ~0ull;
            __syncthreads();
        }
    }

    // ---- hybrid bitonic sort 2048 (asc u64 = score desc, idx asc) ----
    unsigned long long e0 = sb[64 * wid + lane];
    unsigned long long e1 = sb[64 * wid + 32 + lane];
#pragma unroll
    for (int k2 = 2; k2 <= 16; k2 <<= 1) {
#pragma unroll
        for (int j = k2 >> 1; j >= 1; j >>= 1) {
            bool a0 = ((lane & k2) == 0);
            e0 = bx_exch(e0, j, a0, lane);
            e1 = bx_exch(e1, j, a0, lane);
        }
    }
#pragma unroll
    for (int j = 16; j >= 1; j >>= 1) {
        e0 = bx_exch(e0, j, true, lane);
        e1 = bx_exch(e1, j, false, lane);
    }
    {
        bool Aa = ((wid & 1) == 0);
        unsigned long long mn = (e0 < e1) ? e0 : e1;
        unsigned long long mx = (e0 < e1) ? e1 : e0;
        e0 = Aa ? mn : mx; e1 = Aa ? mx : mn;
#pragma unroll
        for (int j = 16; j >= 1; j >>= 1) {
            e0 = bx_exch(e0, j, Aa, lane);
            e1 = bx_exch(e1, j, Aa, lane);
        }
    }
    for (int k2 = 128; k2 <= CAP; k2 <<= 1) {
        sb[64 * wid + lane] = e0;
        sb[64 * wid + 32 + lane] = e1;
        __syncthreads();
        for (int j = k2 >> 1; j >= 64; j >>= 1) {
            int i1 = ((tid & ~(j - 1)) << 1) | (tid & (j - 1));
            int i2 = i1 | j;
            unsigned long long a = sb[i1];
            unsigned long long b = sb[i2];
            bool asc = ((i1 & k2) == 0);
            if ((a > b) == asc) { sb[i1] = b; sb[i2] = a; }
            __syncthreads();
        }
        e0 = sb[64 * wid + lane];
        e1 = sb[64 * wid + 32 + lane];
        bool Aa = (((wid * 64) & k2) == 0);
        unsigned long long mn = (e0 < e1) ? e0 : e1;
        unsigned long long mx = (e0 < e1) ? e1 : e0;
        e0 = Aa ? mn : mx; e1 = Aa ? mx : mn;
#pragma unroll
        for (int j = 16; j >= 1; j >>= 1) {
            e0 = bx_exch(e0, j, Aa, lane);
            e1 = bx_exch(e1, j, Aa, lane);
        }
    }
    sb[64 * wid + lane] = e0;
    sb[64 * wid + 32 + lane] = e1;
    __syncthreads();

    // ---- decode + clip -> global scratch ----
    float sc = 0.0f;
    if (tid < K) {
        unsigned long long kv = sb[tid];
        if (kv != ~0ull) {
            unsigned kk = ~(unsigned)(kv >> 32);
            unsigned u = (kk & 0x80000000u) ? (kk ^ 0x80000000u) : ~kk;
            sc = __uint_as_float(u);
            int idx = (int)(kv & 0xFFFFFFFFull);
            float4 a = reinterpret_cast<const float4*>(anc)[idx];
            float4 r = reinterpret_cast<const float4*>(reg)[idx];
            float wa = a.z - a.x, ha = a.w - a.y;
            float cxa = a.x + 0.5f * wa, cya = a.y + 0.5f * ha;
            float cx = cxa + (r.x * 0.1f) * wa;
            float cy = cya + (r.y * 0.1f) * ha;
            float w = expf(r.z * 0.2f) * wa;
            float h = expf(r.w * 0.2f) * ha;
            float4 b;
            b.x = fminf(fmaxf(cx - 0.5f * w, 0.0f), 1024.0f);
            b.y = fminf(fmaxf(cy - 0.5f * h, 0.0f), 1024.0f);
            b.z = fminf(fmaxf(cx + 0.5f * w, 0.0f), 1024.0f);
            b.w = fminf(fmaxf(cy + 0.5f * h, 0.0f), 1024.0f);
            g_box[c * KP + tid] = b;
            g_score[c * KP + tid] = sc;
        } else {
            g_box[c * KP + tid] = make_float4(0.f, 0.f, 0.f, 0.f);
            g_score[c * KP + tid] = 0.0f;
        }
    } else {
        g_box[c * KP + tid] = make_float4(0.f, 0.f, 0.f, 0.f);
        g_score[c * KP + tid] = 0.0f;
    }
    unsigned bal = __ballot_sync(0xFFFFFFFFu, (tid < K) && (sc > 0.05f));
    if (lane == 0) g_vb[c * 32 + wid] = bal;
}

// ---------------------------------------------------------------------------
// K3: NMS bitmask build (R7-proven inner loop)
// ---------------------------------------------------------------------------
__global__ __launch_bounds__(256, 1) void maskb_v5() {
    __shared__ float4 sbox[KP];
    __shared__ float  sar[KP];
    const int c = blockIdx.y, p = blockIdx.x;
    const int tid = threadIdx.x, lane = tid & 31, wid = tid >> 5;

    for (int i = tid; i < KP; i += 256) {
        float4 b = g_box[c * KP + i];
        sbox[i] = b;
        sar[i] = (b.z - b.x) * (b.w - b.y);
    }
    __syncthreads();

    int gw = p * 8 + wid;          // 0..87 ; 88 * 6 = 528 tasks
    int t0 = gw * 6;
    int bi = 0, rem = t0;
    while (rem >= 32 - bi) { rem -= 32 - bi; ++bi; }
    int bj = bi + rem;

    for (int s = 0; s < 6; ++s) {
        float4 br = sbox[bi * 32 + lane];
        float arE = sar[bi * 32 + lane] + 1e-8f;
        unsigned bits = 0;
#pragma unroll
        for (int jj = 0; jj < 32; ++jj) {
            float4 bc = sbox[bj * 32 + jj];     // broadcast
            float ac = sar[bj * 32 + jj];
            float w = fminf(br.z, bc.z) - fmaxf(br.x, bc.x);
            float h = fminf(br.w, bc.w) - fmaxf(br.y, bc.y);
            float inter = fmaxf(w, 0.0f) * fmaxf(h, 0.0f);
            bool pr = (inter * 3.0f > arE + ac);   // iou > 0.5
            bits |= pr ? (1u << jj) : 0u;
        }
        if (bi == bj) {
            bits &= (0xFFFFFFFEu << lane);         // only jj > lane
            g_diag[c * KP + bi * 32 + lane] = bits;
        }
        g_maskT[(c * 32 + bj) * KP + bi * 32 + lane] = bits;  // coalesced
        if (++bj == 32) { ++bi; bj = bi; }
    }
}

// ---------------------------------------------------------------------------
// K4: serial greedy reduce + outputs (runtime C, K offsets)
// Preload: warp w owns word-column w; coalesced column loads; lower-triangle
// words zero-filled without loading.
// ---------------------------------------------------------------------------
__global__ __launch_bounds__(1024, 1) void reduceo_v5(float* __restrict__ out,
                                                      int C, int K) {
    extern __shared__ unsigned smT[];     // [32 wordcols][1025 rows-padded]
    __shared__ unsigned s_diag[KP];
    __shared__ unsigned s_vb[32];
    __shared__ unsigned s_rm[32];
    const int c = blockIdx.x, tid = threadIdx.x, lane = tid & 31, wid = tid >> 5;

    const uint4* gm4 = reinterpret_cast<const uint4*>(g_maskT + c * 32 * KP);
#pragma unroll
    for (int k = 0; k < 8; ++k) {
        int r4 = k * 32 + lane;              // uint4 index within column (0..255)
        int rb = r4 >> 3;                    // row-block of rows r4*4..r4*4+3
        uint4 v;
        if (wid >= rb) v = gm4[wid * 256 + r4];          // coalesced in-column
        else           v = make_uint4(0u, 0u, 0u, 0u);   // lower triangle: skip load
        unsigned* d = &smT[wid * 1025 + r4 * 4];
        d[0] = v.x; d[1] = v.y; d[2] = v.z; d[3] = v.w;
    }
    s_diag[tid] = g_diag[c * KP + tid];
    if (tid < 32) s_vb[tid] = g_vb[c * 32 + tid];
    __syncthreads();

    if (wid == 0) {
        unsigned removed = 0;
        unsigned vbl = s_vb[lane];
        for (int b = 0; b < 32; ++b) {
            unsigned rmw = __shfl_sync(0xFFFFFFFFu, removed, b);
            unsigned vbw = __shfl_sync(0xFFFFFFFFu, vbl, b);
#pragma unroll
            for (int r = 0; r < 32; ++r) {
                unsigned dgr = s_diag[b * 32 + r];
                unsigned mrr = smT[lane * 1025 + b * 32 + r];
                bool kept = ((vbw >> r) & 1u) && !((rmw >> r) & 1u);
                if (kept) { rmw |= dgr; removed |= mrr; }
            }
        }
        s_rm[lane] = removed;
    }
    __syncthreads();

    if (tid < K) {
        int o = c * K + tid;
        unsigned rw = s_rm[tid >> 5];
        unsigned vb = s_vb[tid >> 5];
        bool kp = ((vb >> (tid & 31)) & 1u) && !((rw >> (tid & 31)) & 1u);
        float sc = g_score[c * KP + tid];
        float4 bb = g_box[c * KP + tid];
        int CK = C * K;
        out[o] = kp ? sc : 0.0f;                                  // scores
        out[CK + o] = kp ? (float)c : -1.0f;                      // labels
        float4 zb = make_float4(0.f, 0.f, 0.f, 0.f);
        float4 ob = kp ? bb : zb;
        out[2 * CK + 4 * o + 0] = ob.x;                           // boxes
        out[2 * CK + 4 * o + 1] = ob.y;
        out[2 * CK + 4 * o + 2] = ob.z;
        out[2 * CK + 4 * o + 3] = ob.w;
        out[6 * CK + o] = kp ? 1.0f : 0.0f;                       // keep
    }
}

// ---------------------------------------------------------------------------
extern "C" void kernel_launch(void* const* d_in, const int* in_sizes, int n_in,
                              void* d_out, int out_size) {
    int cidx = 0;
    for (int i = 1; i < n_in; ++i)
        if (in_sizes[i] > in_sizes[cidx]) cidx = i;
    int o1 = -1, o2 = -1;
    for (int i = 0; i < n_in; ++i)
        if (i != cidx) { if (o1 < 0) o1 = i; else o2 = i; }

    long long A = in_sizes[o1] / 4;
    if (A < 1) A = 1;
    int C = (int)(in_sizes[cidx] / A);
    if (C < 1) C = 1;
    if (C > MAXC) C = MAXC;
    int K = (out_size > 0 && C > 0) ? out_size / (7 * C) : 1000;
    if (K < 1 || K > KP) K = 1000;

    const float* cls = (const float*)d_in[cidx];
    const float* rc  = (const float*)d_in[o1];
    const float* ac  = (const float*)d_in[o2];
    float* out = (float*)d_out;

    initz_v5<<<1, 128>>>(rc, ac);

    collect_v5<<<COLGRID, 256>>>(cls, (int)A, C);

    int selSmem = 16 * 1024 * 4;   // 64KB
    cudaFuncSetAttribute(seldec_v5,
                         cudaFuncAttributeMaxDynamicSharedMemorySize, selSmem);
    seldec_v5<<<C, 1024, selSmem>>>(cls, rc, ac, (int)A, C, K);

    maskb_v5<<<dim3(PARTS, C), 256>>>();

    int redSmem = 32 * 1025 * 4;
    cudaFuncSetAttribute(reduceo_v5,
                         cudaFuncAttributeMaxDynamicSharedMemorySize, redSmem);
    reduceo_v5<<<C, 1024, redSmem>>>(out, C, K);
}